// round 12
// baseline (speedup 1.0000x reference)
#include <cuda_runtime.h>
#include <cuda_bf16.h>
#include <math.h>

#define NN 512
#define GG 8
#define NPG 64
#define SDIM 64
#define VDIM 16
#define EDIM 16
#define LL 5
#define EGC 32256   // 8*64*63

// ---------------- device state ----------------
__device__ float d_E[NN * NPG * EDIM];       // E[i][j][c] = (i*64+j)*16+c
__device__ float d_maskArr[NN * NPG];
__device__ float d_deg[NN];
__device__ float d_s[NN * SDIM];
__device__ float d_vbuf[2][NN * 3 * VDIM];
__device__ float d_pbuf[2][NN * 3];
__device__ float d_A[NN * SDIM];             // s_i @ W1[0:64] + b1  (b1 folded in)
__device__ float d_Bm[NN * SDIM];            // s_j @ W1[64:128]
__device__ float d_f[NN * EDIM];

__device__ __forceinline__ float silu(float x) {
    return x / (1.0f + __expf(-x));
}

__device__ __forceinline__ float reduce64(float* red, int t, float v) {
    red[t] = v; __syncthreads();
    #pragma unroll
    for (int off = 32; off > 0; off >>= 1) {
        if (t < off) red[t] += red[t + off];
        __syncthreads();
    }
    float r = red[0];
    __syncthreads();
    return r;
}

// ---------------- init: mask/deg, state copy, zero E, node-pre layer 0 ----------------
__global__ void k_init(const float* __restrict__ s, const float* __restrict__ v,
                       const float* __restrict__ p, const int* __restrict__ batch,
                       const float* __restrict__ W1, const float* __restrict__ b1,
                       const float* __restrict__ ln_g, const float* __restrict__ ln_b) {
    int n = blockIdx.x, t = threadIdx.x;       // 512 x 64
    int g = n >> 6, base = g << 6;
    __shared__ float red[64];
    __shared__ float sln[64];
    int jn = base + t;
    float dx = p[jn * 3 + 0] - p[n * 3 + 0];
    float dy = p[jn * 3 + 1] - p[n * 3 + 1];
    float dz = p[jn * 3 + 2] - p[n * 3 + 2];
    float dist = sqrtf(fmaxf(dx * dx + dy * dy + dz * dz, 1e-12f));
    float m = (dist < 5.0f && batch[jn] == batch[n] && jn != n) ? 1.0f : 0.0f;
    d_maskArr[n * 64 + t] = m;
    float deg = reduce64(red, t, m);
    if (t == 0) d_deg[n] = fmaxf(deg, 1.0f);
    if (t < 3) d_pbuf[0][n * 3 + t] = p[n * 3 + t];
    for (int idx = t; idx < 1024; idx += 64) d_E[n * 1024 + idx] = 0.0f;

    // node-pre for layer 0: LN
    float sv = s[n * 64 + t];
    float mu = reduce64(red, t, sv) * (1.0f / 64.0f);
    float dv = sv - mu;
    float var = reduce64(red, t, dv * dv) * (1.0f / 64.0f);
    float y = dv * rsqrtf(var + 1e-6f) * ln_g[t] + ln_b[t];
    d_s[n * 64 + t] = y;
    sln[t] = y;
    // v normalize (v=0 -> stays 0)
    float vl = (t < 48) ? v[n * 48 + t] : 0.0f;
    float ss = reduce64(red, t, vl * vl);
    float vnorm = sqrtf(ss * (1.0f / 16.0f) + 1e-6f);
    if (t < 48) d_vbuf[0][n * 48 + t] = vl / vnorm;
    __syncthreads();
    float a = b1[t], b = 0.0f;
    #pragma unroll 8
    for (int c = 0; c < 64; c++) {
        float sc = sln[c];
        a += sc * __ldg(&W1[c * 64 + t]);
        b += sc * __ldg(&W1[(64 + c) * 64 + t]);
    }
    d_A[n * 64 + t] = a;
    d_Bm[n * 64 + t] = b;
}

__global__ void k_scatter(const float* __restrict__ ea, const int* __restrict__ eidx) {
    int idx = blockIdx.x * blockDim.x + threadIdx.x;
    if (idx >= EGC * 16) return;
    int e = idx >> 4, c = idx & 15;
    int s_ = eidx[e], t_ = eidx[EGC + e];
    d_E[(s_ * 64 + (t_ & 63)) * 16 + c] = ea[idx];
}

// ---------------- big pair kernel: one block per node-row, 39KB smem ----------------
struct __align__(16) K2S {
    float h[4096];        // [j][k]
    float W2gvT[1024];    // [vc][k]
    float W1ef[1024];     // [c][k]
    float efr[1024];      // [j][c]
    float genv[1024];     // [j][vc]
    float wts[256];       // [j][w]
    float hw[256];        // [w][k]
    float scratch[256];
    float dj[64]; float cj[64]; float env[64];
    float rn[192];
    float Av[64]; float wd[64]; float wc[64];
    float pg[192];
    float S[4];
    float snew[64]; float hm[64];
};

__global__ void __launch_bounds__(256, 4) k_pair(
    int l, int cur, int doMLP,
    const float* __restrict__ W1, const float* __restrict__ W2,
    const float* __restrict__ b2full,
    const float* __restrict__ Wm1, const float* __restrict__ bm1,
    const float* __restrict__ Wm2, const float* __restrict__ bm2,
    const float* __restrict__ Wpre, const float* __restrict__ bpre) {
    __shared__ K2S sm;
    int i = blockIdx.x;
    int g = i >> 6, il = i & 63;
    int base = g << 6;
    int t = threadIdx.x;
    int nxt = cur ^ 1;
    const float* W1l = W1 + l * 146 * 64;
    const float* W2l = W2 + l * 6208;
    const float* b2l = b2full + l * 97;

    // staging
    for (int idx = t; idx < 1024; idx += 256) {
        int hi = idx >> 6, k = idx & 63;                 // hi = vc or c
        sm.W2gvT[idx] = __ldg(&W2l[k * 97 + 80 + hi]);
        sm.W1ef[idx]  = __ldg(&W1l[(130 + hi) * 64 + k]);
        sm.efr[idx]   = d_E[i * 1024 + idx];
    }
    if (t < 64) {
        sm.wd[t] = __ldg(&W1l[128 * 64 + t]);
        sm.wc[t] = __ldg(&W1l[129 * 64 + t]);
        sm.Av[t] = d_A[i * 64 + t];                      // includes b1
    }
    if (t < 192) sm.pg[t] = d_pbuf[cur][base * 3 + t];
    __syncthreads();

    // geometry (per j)
    if (t < 64) {
        int j = t;
        float pix = sm.pg[il * 3 + 0], piy = sm.pg[il * 3 + 1], piz = sm.pg[il * 3 + 2];
        float pjx = sm.pg[j * 3 + 0],  pjy = sm.pg[j * 3 + 1],  pjz = sm.pg[j * 3 + 2];
        float rx = pjx - pix, ry = pjy - piy, rz = pjz - piz;
        float d = sqrtf(fmaxf(rx * rx + ry * ry + rz * rz, 1e-6f));
        float ni = rsqrtf(pix * pix + piy * piy + piz * piz);
        float nj = rsqrtf(pjx * pjx + pjy * pjy + pjz * pjz);
        sm.dj[j] = d;
        sm.cj[j] = (pix * pjx + piy * pjy + piz * pjz) * ni * nj;
        sm.env[j] = 0.5f * (cospif(d * 0.2f) + 1.0f) * d_maskArr[i * 64 + j];
        float inv = 1.0f / (1.0f + d);
        sm.rn[j * 3 + 0] = rx * inv;
        sm.rn[j * 3 + 1] = ry * inv;
        sm.rn[j * 3 + 2] = rz * inv;
    }
    __syncthreads();

    // h[j][k] = silu(A_i[k] + B_j[k] + d*wd[k] + cos*wc[k] + ef_j @ W1ef)  (4x4 tiles)
    {
        int tj = t >> 4, tk = t & 15;
        int k0 = tk * 4;
        float4 av  = *(const float4*)&sm.Av[k0];
        float4 wdv = *(const float4*)&sm.wd[k0];
        float4 wcv = *(const float4*)&sm.wc[k0];
        float acc[4][4];
        #pragma unroll
        for (int jj = 0; jj < 4; jj++) {
            int j = tj * 4 + jj;
            float djv = sm.dj[j], cjv = sm.cj[j];
            float4 bv = __ldg((const float4*)&d_Bm[(base + j) * 64 + k0]);
            acc[jj][0] = av.x + djv * wdv.x + cjv * wcv.x + bv.x;
            acc[jj][1] = av.y + djv * wdv.y + cjv * wcv.y + bv.y;
            acc[jj][2] = av.z + djv * wdv.z + cjv * wcv.z + bv.z;
            acc[jj][3] = av.w + djv * wdv.w + cjv * wcv.w + bv.w;
        }
        #pragma unroll
        for (int c4 = 0; c4 < 4; c4++) {
            float4 w0 = *(const float4*)&sm.W1ef[(c4 * 4 + 0) * 64 + k0];
            float4 w1 = *(const float4*)&sm.W1ef[(c4 * 4 + 1) * 64 + k0];
            float4 w2 = *(const float4*)&sm.W1ef[(c4 * 4 + 2) * 64 + k0];
            float4 w3 = *(const float4*)&sm.W1ef[(c4 * 4 + 3) * 64 + k0];
            #pragma unroll
            for (int jj = 0; jj < 4; jj++) {
                float4 ev = *(const float4*)&sm.efr[(tj * 4 + jj) * 16 + c4 * 4];
                acc[jj][0] += ev.x * w0.x + ev.y * w1.x + ev.z * w2.x + ev.w * w3.x;
                acc[jj][1] += ev.x * w0.y + ev.y * w1.y + ev.z * w2.y + ev.w * w3.y;
                acc[jj][2] += ev.x * w0.z + ev.y * w1.z + ev.z * w2.z + ev.w * w3.z;
                acc[jj][3] += ev.x * w0.w + ev.y * w1.w + ev.z * w2.w + ev.w * w3.w;
            }
        }
        #pragma unroll
        for (int jj = 0; jj < 4; jj++) {
            float4 hv;
            hv.x = silu(acc[jj][0]); hv.y = silu(acc[jj][1]);
            hv.z = silu(acc[jj][2]); hv.w = silu(acc[jj][3]);
            *(float4*)&sm.h[(tj * 4 + jj) * 64 + k0] = hv;
        }
    }
    __syncthreads();

    // P1: weight table + genv = (h @ W2gv + b2gv) * env   (2x2 tiles)
    {
        int j = t >> 2, w = t & 3;
        sm.wts[t] = (w == 0) ? sm.env[j] : sm.env[j] * sm.rn[j * 3 + (w - 1)];
    }
    {
        int j0 = (t >> 3) * 2, vc0 = (t & 7) * 2;
        float a00 = 0.f, a01 = 0.f, a10 = 0.f, a11 = 0.f;
        #pragma unroll 4
        for (int k4 = 0; k4 < 16; k4++) {
            float4 h0 = *(const float4*)&sm.h[j0 * 64 + k4 * 4];
            float4 h1 = *(const float4*)&sm.h[(j0 + 1) * 64 + k4 * 4];
            float4 g0 = *(const float4*)&sm.W2gvT[vc0 * 64 + k4 * 4];
            float4 g1 = *(const float4*)&sm.W2gvT[(vc0 + 1) * 64 + k4 * 4];
            a00 += h0.x * g0.x + h0.y * g0.y + h0.z * g0.z + h0.w * g0.w;
            a01 += h0.x * g1.x + h0.y * g1.y + h0.z * g1.z + h0.w * g1.w;
            a10 += h1.x * g0.x + h1.y * g0.y + h1.z * g0.z + h1.w * g0.w;
            a11 += h1.x * g1.x + h1.y * g1.y + h1.z * g1.z + h1.w * g1.w;
        }
        float b0 = __ldg(&b2l[80 + vc0]), b1v = __ldg(&b2l[80 + vc0 + 1]);
        float e0 = sm.env[j0], e1 = sm.env[j0 + 1];
        sm.genv[j0 * 16 + vc0]           = (a00 + b0)  * e0;
        sm.genv[j0 * 16 + vc0 + 1]       = (a01 + b1v) * e0;
        sm.genv[(j0 + 1) * 16 + vc0]     = (a10 + b0)  * e1;
        sm.genv[(j0 + 1) * 16 + vc0 + 1] = (a11 + b1v) * e1;
    }
    __syncthreads();

    // P2: hw[w][k] = sum_j wts[j][w] h[j][k];  S[w] = sum_j wts[j][w]
    {
        int k = t & 63, w = t >> 6;
        float acc = 0.f;
        #pragma unroll 8
        for (int j = 0; j < 64; j++) acc += sm.wts[j * 4 + w] * sm.h[j * 64 + k];
        sm.hw[w * 64 + k] = acc;
    }
    if (t < 4) {
        float ss = 0.f;
        #pragma unroll 8
        for (int j = 0; j < 64; j++) ss += sm.wts[j * 4 + t];
        sm.S[t] = ss;
    }
    __syncthreads();

    // T1: s-update partials (4-way split-K, all 256 threads)
    {
        int part = t >> 6, k = t & 63;
        float acc = 0.f;
        #pragma unroll
        for (int q = 0; q < 16; q++) {
            int kp = part * 16 + q;
            acc += sm.hw[kp] * __ldg(&W2l[kp * 97 + k]);
        }
        sm.scratch[part * 64 + k] = acc;
    }
    __syncthreads();

    // T2: combine s; v-update; p-update
    float degi = d_deg[i];
    if (t < 64) {
        float sn = d_s[i * 64 + t] + sm.scratch[t] + sm.scratch[64 + t]
                 + sm.scratch[128 + t] + sm.scratch[192 + t] + __ldg(&b2l[t]) * sm.S[0];
        sm.snew[t] = sn;
        d_s[i * 64 + t] = sn;
    } else if (t < 112) {
        int idx = t - 64, dim = idx >> 4, vc = idx & 15;
        float acc = sm.S[1 + dim] * __ldg(&b2l[64 + vc]);
        #pragma unroll 8
        for (int kp = 0; kp < 64; kp++)
            acc += sm.hw[(1 + dim) * 64 + kp] * __ldg(&W2l[kp * 97 + 64 + vc]);
        float accv = 0.f;
        #pragma unroll 4
        for (int j = 0; j < 64; j++)
            accv += __ldg(&d_vbuf[cur][(base + j) * 48 + dim * 16 + vc]) * sm.genv[j * 16 + vc];
        d_vbuf[nxt][i * 48 + dim * 16 + vc] =
            d_vbuf[cur][i * 48 + dim * 16 + vc] + (acc + accv) / degi;
    } else if (t < 115) {
        int dim = t - 112;
        float acc = sm.S[1 + dim] * __ldg(&b2l[96]);
        #pragma unroll 8
        for (int kp = 0; kp < 64; kp++)
            acc += sm.hw[(1 + dim) * 64 + kp] * __ldg(&W2l[kp * 97 + 96]);
        d_pbuf[nxt][i * 3 + dim] = d_pbuf[cur][i * 3 + dim] + acc / degi;
    }
    __syncthreads();

    // fused node MLP (layers 0..L-2), 4-way split-K
    if (doMLP) {
        {
            int part = t >> 6, k = t & 63;
            float acc = 0.f;
            #pragma unroll
            for (int q = 0; q < 16; q++) {
                int c = part * 16 + q;
                acc += sm.snew[c] * __ldg(&Wm1[l * 4096 + c * 64 + k]);
            }
            sm.scratch[part * 64 + k] = acc;
        }
        __syncthreads();
        if (t < 64)
            sm.hm[t] = silu(sm.scratch[t] + sm.scratch[64 + t] + sm.scratch[128 + t]
                          + sm.scratch[192 + t] + __ldg(&bm1[l * 64 + t]));
        __syncthreads();
        {
            int part = t >> 6, k = t & 63;
            float acc = 0.f;
            #pragma unroll
            for (int q = 0; q < 16; q++) {
                int c = part * 16 + q;
                acc += sm.hm[c] * __ldg(&Wm2[l * 4096 + c * 64 + k]);
            }
            sm.scratch[part * 64 + k] = acc;
        }
        __syncthreads();
        if (t < 64) {
            float s2 = sm.snew[t] + sm.scratch[t] + sm.scratch[64 + t]
                     + sm.scratch[128 + t] + sm.scratch[192 + t] + __ldg(&bm2[l * 64 + t]);
            sm.snew[t] = s2;
            d_s[i * 64 + t] = s2;
        }
        __syncthreads();
    }

    // f = snew @ Wpre + bpre   (16-way split-K)
    {
        int out_ = t & 15, part = t >> 4;
        float acc = 0.f;
        #pragma unroll
        for (int q = 0; q < 4; q++) {
            int k = part * 4 + q;
            acc += sm.snew[k] * __ldg(&Wpre[l * 1024 + k * 16 + out_]);
        }
        sm.scratch[t] = acc;       // scratch[part*16 + out]
    }
    __syncthreads();
    if (t < 16) {
        float acc = __ldg(&bpre[l * 16 + t]);
        #pragma unroll
        for (int q = 0; q < 16; q++) acc += sm.scratch[q * 16 + t];
        d_f[i * 16 + t] = acc;
    }
}

// ---------------- edge MLP update + node-pre for next layer ----------------
__global__ void __launch_bounds__(128) k_edgepre(
    int l, int doPre, int nxt,
    const float* __restrict__ Wpost, const float* __restrict__ bpost,
    const float* __restrict__ W1, const float* __restrict__ b1,
    const float* __restrict__ ln_g, const float* __restrict__ ln_b) {
    int i = blockIdx.x, t = threadIdx.x;   // 512 x 128
    int g = i >> 6, il = i & 63;
    int base = g << 6;
    __shared__ float sf[1024];
    __shared__ float sWp[256];
    __shared__ float sbp[16];
    __shared__ float stmp[1024];
    __shared__ float sln[64];
    __shared__ float red[64];
    for (int idx = t; idx < 1024; idx += 128) sf[idx] = d_f[base * 16 + idx];
    for (int idx = t; idx < 256; idx += 128) sWp[idx] = __ldg(&Wpost[l * 256 + idx]);
    if (t < 16) sbp[t] = __ldg(&bpost[l * 16 + t]);
    __syncthreads();
    for (int idx = t; idx < 1024; idx += 128) {
        int j = idx >> 4, c = idx & 15;
        stmp[idx] = d_E[i * 1024 + idx] + silu(sf[il * 16 + c] + sf[j * 16 + c]);
    }
    __syncthreads();
    for (int idx = t; idx < 1024; idx += 128) {
        int j = idx >> 4, c2 = idx & 15;
        if (d_maskArr[i * 64 + j] > 0.0f) {
            float acc = sbp[c2];
            #pragma unroll
            for (int c = 0; c < 16; c++) acc += stmp[j * 16 + c] * sWp[c * 16 + c2];
            d_E[i * 1024 + j * 16 + c2] = acc;
        }
    }

    if (!doPre) return;
    int lp = l + 1;
    __syncthreads();

    // LayerNorm of s row i (64 values, block-wide reduces)
    float sv = (t < 64) ? d_s[i * 64 + t] : 0.0f;
    if (t < 64) red[t] = sv;
    __syncthreads();
    #pragma unroll
    for (int off = 32; off > 0; off >>= 1) {
        if (t < off) red[t] += red[t + off];
        __syncthreads();
    }
    float mu = red[0] * (1.0f / 64.0f);
    __syncthreads();
    float dv = sv - mu;
    if (t < 64) red[t] = dv * dv;
    __syncthreads();
    #pragma unroll
    for (int off = 32; off > 0; off >>= 1) {
        if (t < off) red[t] += red[t + off];
        __syncthreads();
    }
    float var = red[0] * (1.0f / 64.0f);
    __syncthreads();
    if (t < 64) {
        float y = dv * rsqrtf(var + 1e-6f) * __ldg(&ln_g[lp * 64 + t]) + __ldg(&ln_b[lp * 64 + t]);
        d_s[i * 64 + t] = y;
        sln[t] = y;
    }

    // v normalize (buffer nxt = cur of layer lp)
    float vl = (t < 48) ? d_vbuf[nxt][i * 48 + t] : 0.0f;
    if (t < 64) red[t] = vl * vl;
    __syncthreads();
    #pragma unroll
    for (int off = 32; off > 0; off >>= 1) {
        if (t < off) red[t] += red[t + off];
        __syncthreads();
    }
    float vnorm = sqrtf(red[0] * (1.0f / 16.0f) + 1e-6f);
    if (t < 48) d_vbuf[nxt][i * 48 + t] = vl / vnorm;
    __syncthreads();

    // A (with b1 folded) and B
    const float* W = W1 + lp * 146 * 64;
    if (t < 64) {
        float a = __ldg(&b1[lp * 64 + t]);
        #pragma unroll 8
        for (int c = 0; c < 64; c++) a += sln[c] * __ldg(&W[c * 64 + t]);
        d_A[i * 64 + t] = a;
    } else {
        int k = t - 64;
        float b = 0.f;
        #pragma unroll 8
        for (int c = 0; c < 64; c++) b += sln[c] * __ldg(&W[(64 + c) * 64 + k]);
        d_Bm[i * 64 + k] = b;
    }
}

// ---------------- gather outputs ----------------
__global__ void k_out(float* __restrict__ out, const int* __restrict__ eidx, int fin) {
    int idx = blockIdx.x * blockDim.x + threadIdx.x;
    if (idx < 32768) {
        out[idx] = d_s[idx];
    } else if (idx < 57344) {
        out[idx] = d_vbuf[fin][idx - 32768];
    } else if (idx < 573440) {
        int q = idx - 57344;
        int e = q >> 4, c = q & 15;
        int s_ = eidx[e], t_ = eidx[EGC + e];
        out[idx] = d_E[(s_ * 64 + (t_ & 63)) * 16 + c];
    } else if (idx < 574976) {
        out[idx] = d_pbuf[fin][idx - 573440];
    }
}

extern "C" void kernel_launch(void* const* d_in, const int* in_sizes, int n_in,
                              void* d_out, int out_size) {
    const float* s     = (const float*)d_in[0];
    const float* v     = (const float*)d_in[1];
    const float* p     = (const float*)d_in[2];
    const float* ea    = (const float*)d_in[3];
    const int*   eidx  = (const int*)d_in[4];
    const int*   batch = (const int*)d_in[5];
    const float* ln_g  = (const float*)d_in[6];
    const float* ln_b  = (const float*)d_in[7];
    const float* W1    = (const float*)d_in[8];
    const float* b1    = (const float*)d_in[9];
    const float* W2    = (const float*)d_in[10];
    const float* b2    = (const float*)d_in[11];
    const float* Wm1   = (const float*)d_in[12];
    const float* bm1   = (const float*)d_in[13];
    const float* Wm2   = (const float*)d_in[14];
    const float* bm2   = (const float*)d_in[15];
    const float* Wpre  = (const float*)d_in[16];
    const float* bpre  = (const float*)d_in[17];
    const float* Wpost = (const float*)d_in[18];
    const float* bpost = (const float*)d_in[19];
    float* out = (float*)d_out;

    k_init<<<NN, 64>>>(s, v, p, batch, W1, b1, ln_g, ln_b);
    k_scatter<<<(EGC * 16 + 255) / 256, 256>>>(ea, eidx);

    int cur = 0;
    for (int l = 0; l < LL; l++) {
        k_pair<<<NN, 256>>>(l, cur, (l < LL - 1) ? 1 : 0,
                            W1, W2, b2, Wm1, bm1, Wm2, bm2, Wpre, bpre);
        k_edgepre<<<NN, 128>>>(l, (l < LL - 1) ? 1 : 0, cur ^ 1,
                               Wpost, bpost, W1, b1, ln_g, ln_b);
        cur ^= 1;
    }
    k_out<<<(574976 + 255) / 256, 256>>>(out, eidx, cur);
}

// round 13
// speedup vs baseline: 1.0106x; 1.0106x over previous
#include <cuda_runtime.h>
#include <cuda_bf16.h>
#include <math.h>

#define NN 512
#define GG 8
#define NPG 64
#define SDIM 64
#define VDIM 16
#define EDIM 16
#define LL 5
#define EGC 32256   // 8*64*63

// ---------------- device state ----------------
__device__ float d_E[NN * NPG * EDIM];       // E[i][j][c] = (i*64+j)*16+c
__device__ float d_maskArr[NN * NPG];
__device__ float d_deg[NN];
__device__ float d_s[NN * SDIM];
__device__ float d_vbuf[2][NN * 3 * VDIM];
__device__ float d_pbuf[2][NN * 3];
__device__ float d_A[NN * SDIM];             // s_i @ W1[0:64] + b1  (b1 folded in)
__device__ float d_Bm[NN * SDIM];            // s_j @ W1[64:128]
__device__ float d_f[NN * EDIM];

__device__ __forceinline__ float silu(float x) {
    return x / (1.0f + __expf(-x));
}

__device__ __forceinline__ float reduce64(float* red, int t, float v) {
    red[t] = v; __syncthreads();
    #pragma unroll
    for (int off = 32; off > 0; off >>= 1) {
        if (t < off) red[t] += red[t + off];
        __syncthreads();
    }
    float r = red[0];
    __syncthreads();
    return r;
}

// ---------------- init: mask/deg, state copy, zero E, node-pre layer 0 ----------------
__global__ void k_init(const float* __restrict__ s, const float* __restrict__ v,
                       const float* __restrict__ p, const int* __restrict__ batch,
                       const float* __restrict__ W1, const float* __restrict__ b1,
                       const float* __restrict__ ln_g, const float* __restrict__ ln_b) {
    int n = blockIdx.x, t = threadIdx.x;       // 512 x 64
    int g = n >> 6, base = g << 6;
    __shared__ float red[64];
    __shared__ float sln[64];
    int jn = base + t;
    float dx = p[jn * 3 + 0] - p[n * 3 + 0];
    float dy = p[jn * 3 + 1] - p[n * 3 + 1];
    float dz = p[jn * 3 + 2] - p[n * 3 + 2];
    float dist = sqrtf(fmaxf(dx * dx + dy * dy + dz * dz, 1e-12f));
    float m = (dist < 5.0f && batch[jn] == batch[n] && jn != n) ? 1.0f : 0.0f;
    d_maskArr[n * 64 + t] = m;
    float deg = reduce64(red, t, m);
    if (t == 0) d_deg[n] = fmaxf(deg, 1.0f);
    if (t < 3) d_pbuf[0][n * 3 + t] = p[n * 3 + t];
    for (int idx = t; idx < 1024; idx += 64) d_E[n * 1024 + idx] = 0.0f;

    // node-pre for layer 0: LN
    float sv = s[n * 64 + t];
    float mu = reduce64(red, t, sv) * (1.0f / 64.0f);
    float dv = sv - mu;
    float var = reduce64(red, t, dv * dv) * (1.0f / 64.0f);
    float y = dv * rsqrtf(var + 1e-6f) * ln_g[t] + ln_b[t];
    d_s[n * 64 + t] = y;
    sln[t] = y;
    // v normalize (v=0 -> stays 0)
    float vl = (t < 48) ? v[n * 48 + t] : 0.0f;
    float ss = reduce64(red, t, vl * vl);
    float vnorm = sqrtf(ss * (1.0f / 16.0f) + 1e-6f);
    if (t < 48) d_vbuf[0][n * 48 + t] = vl / vnorm;
    __syncthreads();
    float a = b1[t], b = 0.0f;
    #pragma unroll 8
    for (int c = 0; c < 64; c++) {
        float sc = sln[c];
        a += sc * __ldg(&W1[c * 64 + t]);
        b += sc * __ldg(&W1[(64 + c) * 64 + t]);
    }
    d_A[n * 64 + t] = a;
    d_Bm[n * 64 + t] = b;
}

__global__ void k_scatter(const float* __restrict__ ea, const int* __restrict__ eidx) {
    int idx = blockIdx.x * blockDim.x + threadIdx.x;
    if (idx >= EGC * 16) return;
    int e = idx >> 4, c = idx & 15;
    int s_ = eidx[e], t_ = eidx[EGC + e];
    d_E[(s_ * 64 + (t_ & 63)) * 16 + c] = ea[idx];
}

// ---------------- big pair kernel: one block per node-row, 39KB smem ----------------
struct __align__(16) K2S {
    float h[4096];        // [j][k]
    float W2gvT[1024];    // [vc][k]
    float W1ef[1024];     // [c][k]
    float efr[1024];      // [j][c]
    float genv[1024];     // [j][vc]
    float wts[256];       // [j][w]
    float hw[256];        // [w][k]
    float scratch[256];
    float dj[64]; float cj[64]; float env[64];
    float rn[192];
    float Av[64]; float wd[64]; float wc[64];
    float pg[192];
    float S[4];
    float snew[64]; float hm[64];
};

__global__ void __launch_bounds__(256, 4) k_pair(
    int l, int cur, int doMLP,
    const float* __restrict__ W1, const float* __restrict__ W2,
    const float* __restrict__ b2full,
    const float* __restrict__ Wm1, const float* __restrict__ bm1,
    const float* __restrict__ Wm2, const float* __restrict__ bm2,
    const float* __restrict__ Wpre, const float* __restrict__ bpre) {
    __shared__ K2S sm;
    int i = blockIdx.x;
    int g = i >> 6, il = i & 63;
    int base = g << 6;
    int t = threadIdx.x;
    int nxt = cur ^ 1;
    const float* W1l = W1 + l * 146 * 64;
    const float* W2l = W2 + l * 6208;
    const float* b2l = b2full + l * 97;

    // staging
    for (int idx = t; idx < 1024; idx += 256) {
        int hi = idx >> 6, k = idx & 63;                 // hi = vc or c
        sm.W2gvT[idx] = __ldg(&W2l[k * 97 + 80 + hi]);
        sm.W1ef[idx]  = __ldg(&W1l[(130 + hi) * 64 + k]);
        sm.efr[idx]   = d_E[i * 1024 + idx];
    }
    if (t < 64) {
        sm.wd[t] = __ldg(&W1l[128 * 64 + t]);
        sm.wc[t] = __ldg(&W1l[129 * 64 + t]);
        sm.Av[t] = d_A[i * 64 + t];                      // includes b1
    }
    if (t < 192) sm.pg[t] = d_pbuf[cur][base * 3 + t];
    __syncthreads();

    // geometry (per j)
    if (t < 64) {
        int j = t;
        float pix = sm.pg[il * 3 + 0], piy = sm.pg[il * 3 + 1], piz = sm.pg[il * 3 + 2];
        float pjx = sm.pg[j * 3 + 0],  pjy = sm.pg[j * 3 + 1],  pjz = sm.pg[j * 3 + 2];
        float rx = pjx - pix, ry = pjy - piy, rz = pjz - piz;
        float d = sqrtf(fmaxf(rx * rx + ry * ry + rz * rz, 1e-6f));
        float ni = rsqrtf(pix * pix + piy * piy + piz * piz);
        float nj = rsqrtf(pjx * pjx + pjy * pjy + pjz * pjz);
        sm.dj[j] = d;
        sm.cj[j] = (pix * pjx + piy * pjy + piz * pjz) * ni * nj;
        sm.env[j] = 0.5f * (cospif(d * 0.2f) + 1.0f) * d_maskArr[i * 64 + j];
        float inv = 1.0f / (1.0f + d);
        sm.rn[j * 3 + 0] = rx * inv;
        sm.rn[j * 3 + 1] = ry * inv;
        sm.rn[j * 3 + 2] = rz * inv;
    }
    __syncthreads();

    // h[j][k] = silu(A_i[k] + B_j[k] + d*wd[k] + cos*wc[k] + ef_j @ W1ef)  (4x4 tiles)
    {
        int tj = t >> 4, tk = t & 15;
        int k0 = tk * 4;
        float4 av  = *(const float4*)&sm.Av[k0];
        float4 wdv = *(const float4*)&sm.wd[k0];
        float4 wcv = *(const float4*)&sm.wc[k0];
        float acc[4][4];
        #pragma unroll
        for (int jj = 0; jj < 4; jj++) {
            int j = tj * 4 + jj;
            float djv = sm.dj[j], cjv = sm.cj[j];
            float4 bv = __ldg((const float4*)&d_Bm[(base + j) * 64 + k0]);
            acc[jj][0] = av.x + djv * wdv.x + cjv * wcv.x + bv.x;
            acc[jj][1] = av.y + djv * wdv.y + cjv * wcv.y + bv.y;
            acc[jj][2] = av.z + djv * wdv.z + cjv * wcv.z + bv.z;
            acc[jj][3] = av.w + djv * wdv.w + cjv * wcv.w + bv.w;
        }
        #pragma unroll
        for (int c4 = 0; c4 < 4; c4++) {
            float4 w0 = *(const float4*)&sm.W1ef[(c4 * 4 + 0) * 64 + k0];
            float4 w1 = *(const float4*)&sm.W1ef[(c4 * 4 + 1) * 64 + k0];
            float4 w2 = *(const float4*)&sm.W1ef[(c4 * 4 + 2) * 64 + k0];
            float4 w3 = *(const float4*)&sm.W1ef[(c4 * 4 + 3) * 64 + k0];
            #pragma unroll
            for (int jj = 0; jj < 4; jj++) {
                float4 ev = *(const float4*)&sm.efr[(tj * 4 + jj) * 16 + c4 * 4];
                acc[jj][0] += ev.x * w0.x + ev.y * w1.x + ev.z * w2.x + ev.w * w3.x;
                acc[jj][1] += ev.x * w0.y + ev.y * w1.y + ev.z * w2.y + ev.w * w3.y;
                acc[jj][2] += ev.x * w0.z + ev.y * w1.z + ev.z * w2.z + ev.w * w3.z;
                acc[jj][3] += ev.x * w0.w + ev.y * w1.w + ev.z * w2.w + ev.w * w3.w;
            }
        }
        #pragma unroll
        for (int jj = 0; jj < 4; jj++) {
            float4 hv;
            hv.x = silu(acc[jj][0]); hv.y = silu(acc[jj][1]);
            hv.z = silu(acc[jj][2]); hv.w = silu(acc[jj][3]);
            *(float4*)&sm.h[(tj * 4 + jj) * 64 + k0] = hv;
        }
    }
    __syncthreads();

    // P1: weight table + genv = (h @ W2gv + b2gv) * env   (2x2 tiles)
    {
        int j = t >> 2, w = t & 3;
        sm.wts[t] = (w == 0) ? sm.env[j] : sm.env[j] * sm.rn[j * 3 + (w - 1)];
    }
    {
        int j0 = (t >> 3) * 2, vc0 = (t & 7) * 2;
        float a00 = 0.f, a01 = 0.f, a10 = 0.f, a11 = 0.f;
        #pragma unroll 4
        for (int k4 = 0; k4 < 16; k4++) {
            float4 h0 = *(const float4*)&sm.h[j0 * 64 + k4 * 4];
            float4 h1 = *(const float4*)&sm.h[(j0 + 1) * 64 + k4 * 4];
            float4 g0 = *(const float4*)&sm.W2gvT[vc0 * 64 + k4 * 4];
            float4 g1 = *(const float4*)&sm.W2gvT[(vc0 + 1) * 64 + k4 * 4];
            a00 += h0.x * g0.x + h0.y * g0.y + h0.z * g0.z + h0.w * g0.w;
            a01 += h0.x * g1.x + h0.y * g1.y + h0.z * g1.z + h0.w * g1.w;
            a10 += h1.x * g0.x + h1.y * g0.y + h1.z * g0.z + h1.w * g0.w;
            a11 += h1.x * g1.x + h1.y * g1.y + h1.z * g1.z + h1.w * g1.w;
        }
        float b0 = __ldg(&b2l[80 + vc0]), b1v = __ldg(&b2l[80 + vc0 + 1]);
        float e0 = sm.env[j0], e1 = sm.env[j0 + 1];
        sm.genv[j0 * 16 + vc0]           = (a00 + b0)  * e0;
        sm.genv[j0 * 16 + vc0 + 1]       = (a01 + b1v) * e0;
        sm.genv[(j0 + 1) * 16 + vc0]     = (a10 + b0)  * e1;
        sm.genv[(j0 + 1) * 16 + vc0 + 1] = (a11 + b1v) * e1;
    }
    __syncthreads();

    // P2: hw[w][k] = sum_j wts[j][w] h[j][k];  S[w] = sum_j wts[j][w]
    {
        int k = t & 63, w = t >> 6;
        float acc = 0.f;
        #pragma unroll 8
        for (int j = 0; j < 64; j++) acc += sm.wts[j * 4 + w] * sm.h[j * 64 + k];
        sm.hw[w * 64 + k] = acc;
    }
    if (t < 4) {
        float ss = 0.f;
        #pragma unroll 8
        for (int j = 0; j < 64; j++) ss += sm.wts[j * 4 + t];
        sm.S[t] = ss;
    }
    __syncthreads();

    // T1: s-update partials (4-way split-K, all 256 threads)
    {
        int part = t >> 6, k = t & 63;
        float acc = 0.f;
        #pragma unroll
        for (int q = 0; q < 16; q++) {
            int kp = part * 16 + q;
            acc += sm.hw[kp] * __ldg(&W2l[kp * 97 + k]);
        }
        sm.scratch[part * 64 + k] = acc;
    }
    __syncthreads();

    // T2: combine s; v-update; p-update
    float degi = d_deg[i];
    if (t < 64) {
        float sn = d_s[i * 64 + t] + sm.scratch[t] + sm.scratch[64 + t]
                 + sm.scratch[128 + t] + sm.scratch[192 + t] + __ldg(&b2l[t]) * sm.S[0];
        sm.snew[t] = sn;
        d_s[i * 64 + t] = sn;
    } else if (t < 112) {
        int idx = t - 64, dim = idx >> 4, vc = idx & 15;
        float acc = sm.S[1 + dim] * __ldg(&b2l[64 + vc]);
        #pragma unroll 8
        for (int kp = 0; kp < 64; kp++)
            acc += sm.hw[(1 + dim) * 64 + kp] * __ldg(&W2l[kp * 97 + 64 + vc]);
        float accv = 0.f;
        #pragma unroll 4
        for (int j = 0; j < 64; j++)
            accv += __ldg(&d_vbuf[cur][(base + j) * 48 + dim * 16 + vc]) * sm.genv[j * 16 + vc];
        d_vbuf[nxt][i * 48 + dim * 16 + vc] =
            d_vbuf[cur][i * 48 + dim * 16 + vc] + (acc + accv) / degi;
    } else if (t < 115) {
        int dim = t - 112;
        float acc = sm.S[1 + dim] * __ldg(&b2l[96]);
        #pragma unroll 8
        for (int kp = 0; kp < 64; kp++)
            acc += sm.hw[(1 + dim) * 64 + kp] * __ldg(&W2l[kp * 97 + 96]);
        d_pbuf[nxt][i * 3 + dim] = d_pbuf[cur][i * 3 + dim] + acc / degi;
    }
    __syncthreads();

    // fused node MLP (layers 0..L-2), 4-way split-K
    if (doMLP) {
        {
            int part = t >> 6, k = t & 63;
            float acc = 0.f;
            #pragma unroll
            for (int q = 0; q < 16; q++) {
                int c = part * 16 + q;
                acc += sm.snew[c] * __ldg(&Wm1[l * 4096 + c * 64 + k]);
            }
            sm.scratch[part * 64 + k] = acc;
        }
        __syncthreads();
        if (t < 64)
            sm.hm[t] = silu(sm.scratch[t] + sm.scratch[64 + t] + sm.scratch[128 + t]
                          + sm.scratch[192 + t] + __ldg(&bm1[l * 64 + t]));
        __syncthreads();
        {
            int part = t >> 6, k = t & 63;
            float acc = 0.f;
            #pragma unroll
            for (int q = 0; q < 16; q++) {
                int c = part * 16 + q;
                acc += sm.hm[c] * __ldg(&Wm2[l * 4096 + c * 64 + k]);
            }
            sm.scratch[part * 64 + k] = acc;
        }
        __syncthreads();
        if (t < 64) {
            float s2 = sm.snew[t] + sm.scratch[t] + sm.scratch[64 + t]
                     + sm.scratch[128 + t] + sm.scratch[192 + t] + __ldg(&bm2[l * 64 + t]);
            sm.snew[t] = s2;
            d_s[i * 64 + t] = s2;
        }
        __syncthreads();
    }

    // f = snew @ Wpre + bpre   (16-way split-K)
    {
        int out_ = t & 15, part = t >> 4;
        float acc = 0.f;
        #pragma unroll
        for (int q = 0; q < 4; q++) {
            int k = part * 4 + q;
            acc += sm.snew[k] * __ldg(&Wpre[l * 1024 + k * 16 + out_]);
        }
        sm.scratch[t] = acc;       // scratch[part*16 + out]
    }
    __syncthreads();
    if (t < 16) {
        float acc = __ldg(&bpre[l * 16 + t]);
        #pragma unroll
        for (int q = 0; q < 16; q++) acc += sm.scratch[q * 16 + t];
        d_f[i * 16 + t] = acc;
    }
}

// ---------------- edge MLP update + node-pre for next layer ----------------
__global__ void __launch_bounds__(128) k_edgepre(
    int l, int doPre, int nxt,
    const float* __restrict__ Wpost, const float* __restrict__ bpost,
    const float* __restrict__ W1, const float* __restrict__ b1,
    const float* __restrict__ ln_g, const float* __restrict__ ln_b) {
    int i = blockIdx.x, t = threadIdx.x;   // 512 x 128
    int g = i >> 6, il = i & 63;
    int base = g << 6;
    __shared__ float sf[1024];
    __shared__ float sWp[256];
    __shared__ float sbp[16];
    __shared__ float stmp[1024];
    __shared__ float sln[64];
    __shared__ float red[64];
    for (int idx = t; idx < 1024; idx += 128) sf[idx] = d_f[base * 16 + idx];
    for (int idx = t; idx < 256; idx += 128) sWp[idx] = __ldg(&Wpost[l * 256 + idx]);
    if (t < 16) sbp[t] = __ldg(&bpost[l * 16 + t]);
    __syncthreads();
    for (int idx = t; idx < 1024; idx += 128) {
        int j = idx >> 4, c = idx & 15;
        stmp[idx] = d_E[i * 1024 + idx] + silu(sf[il * 16 + c] + sf[j * 16 + c]);
    }
    __syncthreads();
    for (int idx = t; idx < 1024; idx += 128) {
        int j = idx >> 4, c2 = idx & 15;
        if (d_maskArr[i * 64 + j] > 0.0f) {
            float acc = sbp[c2];
            #pragma unroll
            for (int c = 0; c < 16; c++) acc += stmp[j * 16 + c] * sWp[c * 16 + c2];
            d_E[i * 1024 + j * 16 + c2] = acc;
        }
    }

    if (!doPre) return;
    int lp = l + 1;
    __syncthreads();

    // LayerNorm of s row i (64 values, block-wide reduces)
    float sv = (t < 64) ? d_s[i * 64 + t] : 0.0f;
    if (t < 64) red[t] = sv;
    __syncthreads();
    #pragma unroll
    for (int off = 32; off > 0; off >>= 1) {
        if (t < off) red[t] += red[t + off];
        __syncthreads();
    }
    float mu = red[0] * (1.0f / 64.0f);
    __syncthreads();
    float dv = sv - mu;
    if (t < 64) red[t] = dv * dv;
    __syncthreads();
    #pragma unroll
    for (int off = 32; off > 0; off >>= 1) {
        if (t < off) red[t] += red[t + off];
        __syncthreads();
    }
    float var = red[0] * (1.0f / 64.0f);
    __syncthreads();
    if (t < 64) {
        float y = dv * rsqrtf(var + 1e-6f) * __ldg(&ln_g[lp * 64 + t]) + __ldg(&ln_b[lp * 64 + t]);
        d_s[i * 64 + t] = y;
        sln[t] = y;
    }

    // v normalize (buffer nxt = cur of layer lp)
    float vl = (t < 48) ? d_vbuf[nxt][i * 48 + t] : 0.0f;
    if (t < 64) red[t] = vl * vl;
    __syncthreads();
    #pragma unroll
    for (int off = 32; off > 0; off >>= 1) {
        if (t < off) red[t] += red[t + off];
        __syncthreads();
    }
    float vnorm = sqrtf(red[0] * (1.0f / 16.0f) + 1e-6f);
    if (t < 48) d_vbuf[nxt][i * 48 + t] = vl / vnorm;
    __syncthreads();

    // A (with b1 folded) and B
    const float* W = W1 + lp * 146 * 64;
    if (t < 64) {
        float a = __ldg(&b1[lp * 64 + t]);
        #pragma unroll 8
        for (int c = 0; c < 64; c++) a += sln[c] * __ldg(&W[c * 64 + t]);
        d_A[i * 64 + t] = a;
    } else {
        int k = t - 64;
        float b = 0.f;
        #pragma unroll 8
        for (int c = 0; c < 64; c++) b += sln[c] * __ldg(&W[(64 + c) * 64 + k]);
        d_Bm[i * 64 + k] = b;
    }
}

// ---------------- gather outputs ----------------
__global__ void k_out(float* __restrict__ out, const int* __restrict__ eidx, int fin) {
    int idx = blockIdx.x * blockDim.x + threadIdx.x;
    if (idx < 32768) {
        out[idx] = d_s[idx];
    } else if (idx < 57344) {
        out[idx] = d_vbuf[fin][idx - 32768];
    } else if (idx < 573440) {
        int q = idx - 57344;
        int e = q >> 4, c = q & 15;
        int s_ = eidx[e], t_ = eidx[EGC + e];
        out[idx] = d_E[(s_ * 64 + (t_ & 63)) * 16 + c];
    } else if (idx < 574976) {
        out[idx] = d_pbuf[fin][idx - 573440];
    }
}

extern "C" void kernel_launch(void* const* d_in, const int* in_sizes, int n_in,
                              void* d_out, int out_size) {
    const float* s     = (const float*)d_in[0];
    const float* v     = (const float*)d_in[1];
    const float* p     = (const float*)d_in[2];
    const float* ea    = (const float*)d_in[3];
    const int*   eidx  = (const int*)d_in[4];
    const int*   batch = (const int*)d_in[5];
    const float* ln_g  = (const float*)d_in[6];
    const float* ln_b  = (const float*)d_in[7];
    const float* W1    = (const float*)d_in[8];
    const float* b1    = (const float*)d_in[9];
    const float* W2    = (const float*)d_in[10];
    const float* b2    = (const float*)d_in[11];
    const float* Wm1   = (const float*)d_in[12];
    const float* bm1   = (const float*)d_in[13];
    const float* Wm2   = (const float*)d_in[14];
    const float* bm2   = (const float*)d_in[15];
    const float* Wpre  = (const float*)d_in[16];
    const float* bpre  = (const float*)d_in[17];
    const float* Wpost = (const float*)d_in[18];
    const float* bpost = (const float*)d_in[19];
    float* out = (float*)d_out;

    k_init<<<NN, 64>>>(s, v, p, batch, W1, b1, ln_g, ln_b);
    k_scatter<<<(EGC * 16 + 255) / 256, 256>>>(ea, eidx);

    int cur = 0;
    for (int l = 0; l < LL; l++) {
        k_pair<<<NN, 256>>>(l, cur, (l < LL - 1) ? 1 : 0,
                            W1, W2, b2, Wm1, bm1, Wm2, bm2, Wpre, bpre);
        k_edgepre<<<NN, 128>>>(l, (l < LL - 1) ? 1 : 0, cur ^ 1,
                               Wpost, bpost, W1, b1, ln_g, ln_b);
        cur ^= 1;
    }
    k_out<<<(574976 + 255) / 256, 256>>>(out, eidx, cur);
}

// round 14
// speedup vs baseline: 1.0188x; 1.0081x over previous
#include <cuda_runtime.h>
#include <cuda_bf16.h>
#include <math.h>

#define NN 512
#define GG 8
#define NPG 64
#define SDIM 64
#define VDIM 16
#define EDIM 16
#define LL 5
#define EGC 32256   // 8*64*63

// ---------------- device state ----------------
__device__ float d_E[NN * NPG * EDIM];       // E[i][j][c] = (i*64+j)*16+c
__device__ float d_maskArr[NN * NPG];
__device__ float d_deg[NN];
__device__ float d_s[NN * SDIM];
__device__ float d_vbuf[2][NN * 3 * VDIM];
__device__ float d_pbuf[2][NN * 3];
__device__ float d_A[NN * SDIM];             // s_i @ W1[0:64] + b1  (b1 folded in)
__device__ float d_Bm[NN * SDIM];            // s_j @ W1[64:128]
__device__ float d_f[NN * EDIM];

__device__ __forceinline__ float silu(float x) {
    return x / (1.0f + __expf(-x));
}

__device__ __forceinline__ float reduce64(float* red, int t, float v) {
    red[t] = v; __syncthreads();
    #pragma unroll
    for (int off = 32; off > 0; off >>= 1) {
        if (t < off) red[t] += red[t + off];
        __syncthreads();
    }
    float r = red[0];
    __syncthreads();
    return r;
}

// ---------------- init: mask/deg, state copy, zero E, node-pre layer 0 ----------------
__global__ void k_init(const float* __restrict__ s, const float* __restrict__ v,
                       const float* __restrict__ p, const int* __restrict__ batch,
                       const float* __restrict__ W1, const float* __restrict__ b1,
                       const float* __restrict__ ln_g, const float* __restrict__ ln_b) {
    int n = blockIdx.x, t = threadIdx.x;       // 512 x 64
    int g = n >> 6, base = g << 6;
    __shared__ float red[64];
    __shared__ float sln[64];
    int jn = base + t;
    float dx = p[jn * 3 + 0] - p[n * 3 + 0];
    float dy = p[jn * 3 + 1] - p[n * 3 + 1];
    float dz = p[jn * 3 + 2] - p[n * 3 + 2];
    float dist = sqrtf(fmaxf(dx * dx + dy * dy + dz * dz, 1e-12f));
    float m = (dist < 5.0f && batch[jn] == batch[n] && jn != n) ? 1.0f : 0.0f;
    d_maskArr[n * 64 + t] = m;
    float deg = reduce64(red, t, m);
    if (t == 0) d_deg[n] = fmaxf(deg, 1.0f);
    if (t < 3) d_pbuf[0][n * 3 + t] = p[n * 3 + t];
    for (int idx = t; idx < 1024; idx += 64) d_E[n * 1024 + idx] = 0.0f;

    // node-pre for layer 0: LN
    float sv = s[n * 64 + t];
    float mu = reduce64(red, t, sv) * (1.0f / 64.0f);
    float dv = sv - mu;
    float var = reduce64(red, t, dv * dv) * (1.0f / 64.0f);
    float y = dv * rsqrtf(var + 1e-6f) * ln_g[t] + ln_b[t];
    d_s[n * 64 + t] = y;
    sln[t] = y;
    // v normalize (v=0 -> stays 0)
    float vl = (t < 48) ? v[n * 48 + t] : 0.0f;
    float ss = reduce64(red, t, vl * vl);
    float vnorm = sqrtf(ss * (1.0f / 16.0f) + 1e-6f);
    if (t < 48) d_vbuf[0][n * 48 + t] = vl / vnorm;
    __syncthreads();
    float a = b1[t], b = 0.0f;
    #pragma unroll 8
    for (int c = 0; c < 64; c++) {
        float sc = sln[c];
        a += sc * __ldg(&W1[c * 64 + t]);
        b += sc * __ldg(&W1[(64 + c) * 64 + t]);
    }
    d_A[n * 64 + t] = a;
    d_Bm[n * 64 + t] = b;
}

__global__ void k_scatter(const float* __restrict__ ea, const int* __restrict__ eidx) {
    int idx = blockIdx.x * blockDim.x + threadIdx.x;
    if (idx >= EGC * 16) return;
    int e = idx >> 4, c = idx & 15;
    int s_ = eidx[e], t_ = eidx[EGC + e];
    d_E[(s_ * 64 + (t_ & 63)) * 16 + c] = ea[idx];
}

// ---------------- big pair kernel: one block per node-row, 39KB smem ----------------
struct __align__(16) K2S {
    float h[4096];        // [j][k]
    float W2gvT[1024];    // [vc][k]
    float W1ef[1024];     // [c][k]
    float efr[1024];      // [j][c]
    float genv[1024];     // [j][vc]
    float wts[256];       // [j][w]
    float hw[256];        // [w][k]
    float scratch[256];
    float dj[64]; float cj[64]; float env[64];
    float rn[192];
    float Av[64]; float wd[64]; float wc[64];
    float pg[192];
    float S[4];
    float snew[64]; float hm[64];
};

__global__ void __launch_bounds__(256, 4) k_pair(
    int l, int cur, int doMLP,
    const float* __restrict__ W1, const float* __restrict__ W2,
    const float* __restrict__ b2full,
    const float* __restrict__ Wm1, const float* __restrict__ bm1,
    const float* __restrict__ Wm2, const float* __restrict__ bm2,
    const float* __restrict__ Wpre, const float* __restrict__ bpre) {
    __shared__ K2S sm;
    int i = blockIdx.x;
    int g = i >> 6, il = i & 63;
    int base = g << 6;
    int t = threadIdx.x;
    int nxt = cur ^ 1;
    const float* W1l = W1 + l * 146 * 64;
    const float* W2l = W2 + l * 6208;
    const float* b2l = b2full + l * 97;

    // staging
    for (int idx = t; idx < 1024; idx += 256) {
        int hi = idx >> 6, k = idx & 63;                 // hi = vc or c
        sm.W2gvT[idx] = __ldg(&W2l[k * 97 + 80 + hi]);
        sm.W1ef[idx]  = __ldg(&W1l[(130 + hi) * 64 + k]);
        sm.efr[idx]   = d_E[i * 1024 + idx];
    }
    if (t < 64) {
        sm.wd[t] = __ldg(&W1l[128 * 64 + t]);
        sm.wc[t] = __ldg(&W1l[129 * 64 + t]);
        sm.Av[t] = d_A[i * 64 + t];                      // includes b1
    }
    if (t < 192) sm.pg[t] = d_pbuf[cur][base * 3 + t];
    __syncthreads();

    // geometry (per j)
    if (t < 64) {
        int j = t;
        float pix = sm.pg[il * 3 + 0], piy = sm.pg[il * 3 + 1], piz = sm.pg[il * 3 + 2];
        float pjx = sm.pg[j * 3 + 0],  pjy = sm.pg[j * 3 + 1],  pjz = sm.pg[j * 3 + 2];
        float rx = pjx - pix, ry = pjy - piy, rz = pjz - piz;
        float d = sqrtf(fmaxf(rx * rx + ry * ry + rz * rz, 1e-6f));
        float ni = rsqrtf(pix * pix + piy * piy + piz * piz);
        float nj = rsqrtf(pjx * pjx + pjy * pjy + pjz * pjz);
        sm.dj[j] = d;
        sm.cj[j] = (pix * pjx + piy * pjy + piz * pjz) * ni * nj;
        sm.env[j] = 0.5f * (cospif(d * 0.2f) + 1.0f) * d_maskArr[i * 64 + j];
        float inv = 1.0f / (1.0f + d);
        sm.rn[j * 3 + 0] = rx * inv;
        sm.rn[j * 3 + 1] = ry * inv;
        sm.rn[j * 3 + 2] = rz * inv;
    }
    __syncthreads();

    // h[j][k] = silu(A_i[k] + B_j[k] + d*wd[k] + cos*wc[k] + ef_j @ W1ef)  (4x4 tiles)
    {
        int tj = t >> 4, tk = t & 15;
        int k0 = tk * 4;
        float4 av  = *(const float4*)&sm.Av[k0];
        float4 wdv = *(const float4*)&sm.wd[k0];
        float4 wcv = *(const float4*)&sm.wc[k0];
        float acc[4][4];
        #pragma unroll
        for (int jj = 0; jj < 4; jj++) {
            int j = tj * 4 + jj;
            float djv = sm.dj[j], cjv = sm.cj[j];
            float4 bv = __ldg((const float4*)&d_Bm[(base + j) * 64 + k0]);
            acc[jj][0] = av.x + djv * wdv.x + cjv * wcv.x + bv.x;
            acc[jj][1] = av.y + djv * wdv.y + cjv * wcv.y + bv.y;
            acc[jj][2] = av.z + djv * wdv.z + cjv * wcv.z + bv.z;
            acc[jj][3] = av.w + djv * wdv.w + cjv * wcv.w + bv.w;
        }
        #pragma unroll
        for (int c4 = 0; c4 < 4; c4++) {
            float4 w0 = *(const float4*)&sm.W1ef[(c4 * 4 + 0) * 64 + k0];
            float4 w1 = *(const float4*)&sm.W1ef[(c4 * 4 + 1) * 64 + k0];
            float4 w2 = *(const float4*)&sm.W1ef[(c4 * 4 + 2) * 64 + k0];
            float4 w3 = *(const float4*)&sm.W1ef[(c4 * 4 + 3) * 64 + k0];
            #pragma unroll
            for (int jj = 0; jj < 4; jj++) {
                float4 ev = *(const float4*)&sm.efr[(tj * 4 + jj) * 16 + c4 * 4];
                acc[jj][0] += ev.x * w0.x + ev.y * w1.x + ev.z * w2.x + ev.w * w3.x;
                acc[jj][1] += ev.x * w0.y + ev.y * w1.y + ev.z * w2.y + ev.w * w3.y;
                acc[jj][2] += ev.x * w0.z + ev.y * w1.z + ev.z * w2.z + ev.w * w3.z;
                acc[jj][3] += ev.x * w0.w + ev.y * w1.w + ev.z * w2.w + ev.w * w3.w;
            }
        }
        #pragma unroll
        for (int jj = 0; jj < 4; jj++) {
            float4 hv;
            hv.x = silu(acc[jj][0]); hv.y = silu(acc[jj][1]);
            hv.z = silu(acc[jj][2]); hv.w = silu(acc[jj][3]);
            *(float4*)&sm.h[(tj * 4 + jj) * 64 + k0] = hv;
        }
    }
    __syncthreads();

    // P1: weight table + genv = (h @ W2gv + b2gv) * env   (2x2 tiles)
    {
        int j = t >> 2, w = t & 3;
        sm.wts[t] = (w == 0) ? sm.env[j] : sm.env[j] * sm.rn[j * 3 + (w - 1)];
    }
    {
        int j0 = (t >> 3) * 2, vc0 = (t & 7) * 2;
        float a00 = 0.f, a01 = 0.f, a10 = 0.f, a11 = 0.f;
        #pragma unroll 4
        for (int k4 = 0; k4 < 16; k4++) {
            float4 h0 = *(const float4*)&sm.h[j0 * 64 + k4 * 4];
            float4 h1 = *(const float4*)&sm.h[(j0 + 1) * 64 + k4 * 4];
            float4 g0 = *(const float4*)&sm.W2gvT[vc0 * 64 + k4 * 4];
            float4 g1 = *(const float4*)&sm.W2gvT[(vc0 + 1) * 64 + k4 * 4];
            a00 += h0.x * g0.x + h0.y * g0.y + h0.z * g0.z + h0.w * g0.w;
            a01 += h0.x * g1.x + h0.y * g1.y + h0.z * g1.z + h0.w * g1.w;
            a10 += h1.x * g0.x + h1.y * g0.y + h1.z * g0.z + h1.w * g0.w;
            a11 += h1.x * g1.x + h1.y * g1.y + h1.z * g1.z + h1.w * g1.w;
        }
        float b0 = __ldg(&b2l[80 + vc0]), b1v = __ldg(&b2l[80 + vc0 + 1]);
        float e0 = sm.env[j0], e1 = sm.env[j0 + 1];
        sm.genv[j0 * 16 + vc0]           = (a00 + b0)  * e0;
        sm.genv[j0 * 16 + vc0 + 1]       = (a01 + b1v) * e0;
        sm.genv[(j0 + 1) * 16 + vc0]     = (a10 + b0)  * e1;
        sm.genv[(j0 + 1) * 16 + vc0 + 1] = (a11 + b1v) * e1;
    }
    __syncthreads();

    // P2: hw[w][k] = sum_j wts[j][w] h[j][k];  S[w] = sum_j wts[j][w]
    {
        int k = t & 63, w = t >> 6;
        float acc = 0.f;
        #pragma unroll 8
        for (int j = 0; j < 64; j++) acc += sm.wts[j * 4 + w] * sm.h[j * 64 + k];
        sm.hw[w * 64 + k] = acc;
    }
    if (t < 4) {
        float ss = 0.f;
        #pragma unroll 8
        for (int j = 0; j < 64; j++) ss += sm.wts[j * 4 + t];
        sm.S[t] = ss;
    }
    __syncthreads();

    // T1: s-update partials (4-way split-K, all 256 threads)
    {
        int part = t >> 6, k = t & 63;
        float acc = 0.f;
        #pragma unroll
        for (int q = 0; q < 16; q++) {
            int kp = part * 16 + q;
            acc += sm.hw[kp] * __ldg(&W2l[kp * 97 + k]);
        }
        sm.scratch[part * 64 + k] = acc;
    }
    __syncthreads();

    // T2: combine s; v-update; p-update
    float degi = d_deg[i];
    if (t < 64) {
        float sn = d_s[i * 64 + t] + sm.scratch[t] + sm.scratch[64 + t]
                 + sm.scratch[128 + t] + sm.scratch[192 + t] + __ldg(&b2l[t]) * sm.S[0];
        sm.snew[t] = sn;
        d_s[i * 64 + t] = sn;
    } else if (t < 112) {
        int idx = t - 64, dim = idx >> 4, vc = idx & 15;
        float acc = sm.S[1 + dim] * __ldg(&b2l[64 + vc]);
        #pragma unroll 8
        for (int kp = 0; kp < 64; kp++)
            acc += sm.hw[(1 + dim) * 64 + kp] * __ldg(&W2l[kp * 97 + 64 + vc]);
        float accv = 0.f;
        #pragma unroll 4
        for (int j = 0; j < 64; j++)
            accv += __ldg(&d_vbuf[cur][(base + j) * 48 + dim * 16 + vc]) * sm.genv[j * 16 + vc];
        d_vbuf[nxt][i * 48 + dim * 16 + vc] =
            d_vbuf[cur][i * 48 + dim * 16 + vc] + (acc + accv) / degi;
    } else if (t < 115) {
        int dim = t - 112;
        float acc = sm.S[1 + dim] * __ldg(&b2l[96]);
        #pragma unroll 8
        for (int kp = 0; kp < 64; kp++)
            acc += sm.hw[(1 + dim) * 64 + kp] * __ldg(&W2l[kp * 97 + 96]);
        d_pbuf[nxt][i * 3 + dim] = d_pbuf[cur][i * 3 + dim] + acc / degi;
    }
    __syncthreads();

    // fused node MLP (layers 0..L-2), 4-way split-K
    if (doMLP) {
        {
            int part = t >> 6, k = t & 63;
            float acc = 0.f;
            #pragma unroll
            for (int q = 0; q < 16; q++) {
                int c = part * 16 + q;
                acc += sm.snew[c] * __ldg(&Wm1[l * 4096 + c * 64 + k]);
            }
            sm.scratch[part * 64 + k] = acc;
        }
        __syncthreads();
        if (t < 64)
            sm.hm[t] = silu(sm.scratch[t] + sm.scratch[64 + t] + sm.scratch[128 + t]
                          + sm.scratch[192 + t] + __ldg(&bm1[l * 64 + t]));
        __syncthreads();
        {
            int part = t >> 6, k = t & 63;
            float acc = 0.f;
            #pragma unroll
            for (int q = 0; q < 16; q++) {
                int c = part * 16 + q;
                acc += sm.hm[c] * __ldg(&Wm2[l * 4096 + c * 64 + k]);
            }
            sm.scratch[part * 64 + k] = acc;
        }
        __syncthreads();
        if (t < 64) {
            float s2 = sm.snew[t] + sm.scratch[t] + sm.scratch[64 + t]
                     + sm.scratch[128 + t] + sm.scratch[192 + t] + __ldg(&bm2[l * 64 + t]);
            sm.snew[t] = s2;
            d_s[i * 64 + t] = s2;
        }
        __syncthreads();
    }

    // f = snew @ Wpre + bpre   (16-way split-K)
    {
        int out_ = t & 15, part = t >> 4;
        float acc = 0.f;
        #pragma unroll
        for (int q = 0; q < 4; q++) {
            int k = part * 4 + q;
            acc += sm.snew[k] * __ldg(&Wpre[l * 1024 + k * 16 + out_]);
        }
        sm.scratch[t] = acc;       // scratch[part*16 + out]
    }
    __syncthreads();
    if (t < 16) {
        float acc = __ldg(&bpre[l * 16 + t]);
        #pragma unroll
        for (int q = 0; q < 16; q++) acc += sm.scratch[q * 16 + t];
        d_f[i * 16 + t] = acc;
    }
}

// ---------------- edge MLP update + node-pre for next layer ----------------
__global__ void __launch_bounds__(128) k_edgepre(
    int l, int doPre, int nxt,
    const float* __restrict__ Wpost, const float* __restrict__ bpost,
    const float* __restrict__ W1, const float* __restrict__ b1,
    const float* __restrict__ ln_g, const float* __restrict__ ln_b) {
    int i = blockIdx.x, t = threadIdx.x;   // 512 x 128
    int g = i >> 6, il = i & 63;
    int base = g << 6;
    __shared__ float sf[1024];
    __shared__ float sWp[256];
    __shared__ float sbp[16];
    __shared__ float stmp[1024];
    __shared__ float sln[64];
    __shared__ float red[64];
    for (int idx = t; idx < 1024; idx += 128) sf[idx] = d_f[base * 16 + idx];
    for (int idx = t; idx < 256; idx += 128) sWp[idx] = __ldg(&Wpost[l * 256 + idx]);
    if (t < 16) sbp[t] = __ldg(&bpost[l * 16 + t]);
    __syncthreads();
    for (int idx = t; idx < 1024; idx += 128) {
        int j = idx >> 4, c = idx & 15;
        stmp[idx] = d_E[i * 1024 + idx] + silu(sf[il * 16 + c] + sf[j * 16 + c]);
    }
    __syncthreads();
    for (int idx = t; idx < 1024; idx += 128) {
        int j = idx >> 4, c2 = idx & 15;
        if (d_maskArr[i * 64 + j] > 0.0f) {
            float acc = sbp[c2];
            #pragma unroll
            for (int c = 0; c < 16; c++) acc += stmp[j * 16 + c] * sWp[c * 16 + c2];
            d_E[i * 1024 + j * 16 + c2] = acc;
        }
    }

    if (!doPre) return;
    int lp = l + 1;
    __syncthreads();

    // LayerNorm of s row i (64 values, block-wide reduces)
    float sv = (t < 64) ? d_s[i * 64 + t] : 0.0f;
    if (t < 64) red[t] = sv;
    __syncthreads();
    #pragma unroll
    for (int off = 32; off > 0; off >>= 1) {
        if (t < off) red[t] += red[t + off];
        __syncthreads();
    }
    float mu = red[0] * (1.0f / 64.0f);
    __syncthreads();
    float dv = sv - mu;
    if (t < 64) red[t] = dv * dv;
    __syncthreads();
    #pragma unroll
    for (int off = 32; off > 0; off >>= 1) {
        if (t < off) red[t] += red[t + off];
        __syncthreads();
    }
    float var = red[0] * (1.0f / 64.0f);
    __syncthreads();
    if (t < 64) {
        float y = dv * rsqrtf(var + 1e-6f) * __ldg(&ln_g[lp * 64 + t]) + __ldg(&ln_b[lp * 64 + t]);
        d_s[i * 64 + t] = y;
        sln[t] = y;
    }

    // v normalize (buffer nxt = cur of layer lp)
    float vl = (t < 48) ? d_vbuf[nxt][i * 48 + t] : 0.0f;
    if (t < 64) red[t] = vl * vl;
    __syncthreads();
    #pragma unroll
    for (int off = 32; off > 0; off >>= 1) {
        if (t < off) red[t] += red[t + off];
        __syncthreads();
    }
    float vnorm = sqrtf(red[0] * (1.0f / 16.0f) + 1e-6f);
    if (t < 48) d_vbuf[nxt][i * 48 + t] = vl / vnorm;
    __syncthreads();

    // A (with b1 folded) and B
    const float* W = W1 + lp * 146 * 64;
    if (t < 64) {
        float a = __ldg(&b1[lp * 64 + t]);
        #pragma unroll 8
        for (int c = 0; c < 64; c++) a += sln[c] * __ldg(&W[c * 64 + t]);
        d_A[i * 64 + t] = a;
    } else {
        int k = t - 64;
        float b = 0.f;
        #pragma unroll 8
        for (int c = 0; c < 64; c++) b += sln[c] * __ldg(&W[(64 + c) * 64 + k]);
        d_Bm[i * 64 + k] = b;
    }
}

// ---------------- gather outputs ----------------
__global__ void k_out(float* __restrict__ out, const int* __restrict__ eidx, int fin) {
    int idx = blockIdx.x * blockDim.x + threadIdx.x;
    if (idx < 32768) {
        out[idx] = d_s[idx];
    } else if (idx < 57344) {
        out[idx] = d_vbuf[fin][idx - 32768];
    } else if (idx < 573440) {
        int q = idx - 57344;
        int e = q >> 4, c = q & 15;
        int s_ = eidx[e], t_ = eidx[EGC + e];
        out[idx] = d_E[(s_ * 64 + (t_ & 63)) * 16 + c];
    } else if (idx < 574976) {
        out[idx] = d_pbuf[fin][idx - 573440];
    }
}

extern "C" void kernel_launch(void* const* d_in, const int* in_sizes, int n_in,
                              void* d_out, int out_size) {
    const float* s     = (const float*)d_in[0];
    const float* v     = (const float*)d_in[1];
    const float* p     = (const float*)d_in[2];
    const float* ea    = (const float*)d_in[3];
    const int*   eidx  = (const int*)d_in[4];
    const int*   batch = (const int*)d_in[5];
    const float* ln_g  = (const float*)d_in[6];
    const float* ln_b  = (const float*)d_in[7];
    const float* W1    = (const float*)d_in[8];
    const float* b1    = (const float*)d_in[9];
    const float* W2    = (const float*)d_in[10];
    const float* b2    = (const float*)d_in[11];
    const float* Wm1   = (const float*)d_in[12];
    const float* bm1   = (const float*)d_in[13];
    const float* Wm2   = (const float*)d_in[14];
    const float* bm2   = (const float*)d_in[15];
    const float* Wpre  = (const float*)d_in[16];
    const float* bpre  = (const float*)d_in[17];
    const float* Wpost = (const float*)d_in[18];
    const float* bpost = (const float*)d_in[19];
    float* out = (float*)d_out;

    k_init<<<NN, 64>>>(s, v, p, batch, W1, b1, ln_g, ln_b);
    k_scatter<<<(EGC * 16 + 255) / 256, 256>>>(ea, eidx);

    int cur = 0;
    for (int l = 0; l < LL; l++) {
        k_pair<<<NN, 256>>>(l, cur, (l < LL - 1) ? 1 : 0,
                            W1, W2, b2, Wm1, bm1, Wm2, bm2, Wpre, bpre);
        k_edgepre<<<NN, 128>>>(l, (l < LL - 1) ? 1 : 0, cur ^ 1,
                               Wpost, bpost, W1, b1, ln_g, ln_b);
        cur ^= 1;
    }
    k_out<<<(574976 + 255) / 256, 256>>>(out, eidx, cur);
}

// round 16
// speedup vs baseline: 1.0194x; 1.0006x over previous
#include <cuda_runtime.h>
#include <cuda_bf16.h>
#include <math.h>

#define NN 512
#define GG 8
#define NPG 64
#define SDIM 64
#define VDIM 16
#define EDIM 16
#define LL 5
#define EGC 32256   // 8*64*63

// ---------------- device state ----------------
__device__ float d_E[NN * NPG * EDIM];       // E[i][j][c] = (i*64+j)*16+c
__device__ float d_maskArr[NN * NPG];
__device__ float d_deg[NN];
__device__ float d_s[NN * SDIM];
__device__ float d_vbuf[2][NN * 3 * VDIM];
__device__ float d_pbuf[2][NN * 3];
__device__ float d_A[NN * SDIM];             // s_i @ W1[0:64] + b1  (b1 folded in)
__device__ float d_Bm[NN * SDIM];            // s_j @ W1[64:128]
__device__ float d_f[NN * EDIM];

__device__ __forceinline__ float silu(float x) {
    return x / (1.0f + __expf(-x));
}

__device__ __forceinline__ float reduce64(float* red, int t, float v) {
    red[t] = v; __syncthreads();
    #pragma unroll
    for (int off = 32; off > 0; off >>= 1) {
        if (t < off) red[t] += red[t + off];
        __syncthreads();
    }
    float r = red[0];
    __syncthreads();
    return r;
}

// ---------------- init: mask/deg, state copy, zero E, node-pre layer 0 ----------------
__global__ void k_init(const float* __restrict__ s, const float* __restrict__ v,
                       const float* __restrict__ p, const int* __restrict__ batch,
                       const float* __restrict__ W1, const float* __restrict__ b1,
                       const float* __restrict__ ln_g, const float* __restrict__ ln_b) {
    int n = blockIdx.x, t = threadIdx.x;       // 512 x 64
    int g = n >> 6, base = g << 6;
    __shared__ float red[64];
    __shared__ float sln[64];
    int jn = base + t;
    float dx = p[jn * 3 + 0] - p[n * 3 + 0];
    float dy = p[jn * 3 + 1] - p[n * 3 + 1];
    float dz = p[jn * 3 + 2] - p[n * 3 + 2];
    float dist = sqrtf(fmaxf(dx * dx + dy * dy + dz * dz, 1e-12f));
    float m = (dist < 5.0f && batch[jn] == batch[n] && jn != n) ? 1.0f : 0.0f;
    d_maskArr[n * 64 + t] = m;
    float deg = reduce64(red, t, m);
    if (t == 0) d_deg[n] = fmaxf(deg, 1.0f);
    if (t < 3) d_pbuf[0][n * 3 + t] = p[n * 3 + t];
    for (int idx = t; idx < 1024; idx += 64) d_E[n * 1024 + idx] = 0.0f;

    // node-pre for layer 0: LN
    float sv = s[n * 64 + t];
    float mu = reduce64(red, t, sv) * (1.0f / 64.0f);
    float dv = sv - mu;
    float var = reduce64(red, t, dv * dv) * (1.0f / 64.0f);
    float y = dv * rsqrtf(var + 1e-6f) * ln_g[t] + ln_b[t];
    d_s[n * 64 + t] = y;
    sln[t] = y;
    // v normalize (v=0 -> stays 0)
    float vl = (t < 48) ? v[n * 48 + t] : 0.0f;
    float ss = reduce64(red, t, vl * vl);
    float vnorm = sqrtf(ss * (1.0f / 16.0f) + 1e-6f);
    if (t < 48) d_vbuf[0][n * 48 + t] = vl / vnorm;
    __syncthreads();
    float a = b1[t], b = 0.0f;
    #pragma unroll 8
    for (int c = 0; c < 64; c++) {
        float sc = sln[c];
        a += sc * __ldg(&W1[c * 64 + t]);
        b += sc * __ldg(&W1[(64 + c) * 64 + t]);
    }
    d_A[n * 64 + t] = a;
    d_Bm[n * 64 + t] = b;
}

__global__ void k_scatter(const float* __restrict__ ea, const int* __restrict__ eidx) {
    int idx = blockIdx.x * blockDim.x + threadIdx.x;
    if (idx >= EGC * 16) return;
    int e = idx >> 4, c = idx & 15;
    int s_ = eidx[e], t_ = eidx[EGC + e];
    d_E[(s_ * 64 + (t_ & 63)) * 16 + c] = ea[idx];
}

// ---------------- big pair kernel: one block per node-row, 39KB smem ----------------
struct __align__(16) K2S {
    float h[4096];        // [j][k]
    float W2gvT[1024];    // [vc][k]
    float W1ef[1024];     // [c][k]
    float efr[1024];      // [j][c]
    float genv[1024];     // [j][vc]
    float wts[256];       // [j][w]
    float hw[256];        // [w][k]
    float scratch[256];
    float dj[64]; float cj[64]; float env[64];
    float rn[192];
    float Av[64]; float wd[64]; float wc[64];
    float pg[192];
    float S[4];
    float snew[64]; float hm[64];
};

__global__ void __launch_bounds__(256, 4) k_pair(
    int l, int cur, int doMLP,
    const float* __restrict__ W1, const float* __restrict__ W2,
    const float* __restrict__ b2full,
    const float* __restrict__ Wm1, const float* __restrict__ bm1,
    const float* __restrict__ Wm2, const float* __restrict__ bm2,
    const float* __restrict__ Wpre, const float* __restrict__ bpre) {
    __shared__ K2S sm;
    int i = blockIdx.x;
    int g = i >> 6, il = i & 63;
    int base = g << 6;
    int t = threadIdx.x;
    int nxt = cur ^ 1;
    const float* W1l = W1 + l * 146 * 64;
    const float* W2l = W2 + l * 6208;
    const float* b2l = b2full + l * 97;

    // staging
    for (int idx = t; idx < 1024; idx += 256) {
        int hi = idx >> 6, k = idx & 63;                 // hi = vc or c
        sm.W2gvT[idx] = __ldg(&W2l[k * 97 + 80 + hi]);
        sm.W1ef[idx]  = __ldg(&W1l[(130 + hi) * 64 + k]);
        sm.efr[idx]   = d_E[i * 1024 + idx];
    }
    if (t < 64) {
        sm.wd[t] = __ldg(&W1l[128 * 64 + t]);
        sm.wc[t] = __ldg(&W1l[129 * 64 + t]);
        sm.Av[t] = d_A[i * 64 + t];                      // includes b1
    }
    if (t < 192) sm.pg[t] = d_pbuf[cur][base * 3 + t];
    __syncthreads();

    // geometry (per j)
    if (t < 64) {
        int j = t;
        float pix = sm.pg[il * 3 + 0], piy = sm.pg[il * 3 + 1], piz = sm.pg[il * 3 + 2];
        float pjx = sm.pg[j * 3 + 0],  pjy = sm.pg[j * 3 + 1],  pjz = sm.pg[j * 3 + 2];
        float rx = pjx - pix, ry = pjy - piy, rz = pjz - piz;
        float d = sqrtf(fmaxf(rx * rx + ry * ry + rz * rz, 1e-6f));
        float ni = rsqrtf(pix * pix + piy * piy + piz * piz);
        float nj = rsqrtf(pjx * pjx + pjy * pjy + pjz * pjz);
        sm.dj[j] = d;
        sm.cj[j] = (pix * pjx + piy * pjy + piz * pjz) * ni * nj;
        sm.env[j] = 0.5f * (cospif(d * 0.2f) + 1.0f) * d_maskArr[i * 64 + j];
        float inv = 1.0f / (1.0f + d);
        sm.rn[j * 3 + 0] = rx * inv;
        sm.rn[j * 3 + 1] = ry * inv;
        sm.rn[j * 3 + 2] = rz * inv;
    }
    __syncthreads();

    // h[j][k] = silu(A_i[k] + B_j[k] + d*wd[k] + cos*wc[k] + ef_j @ W1ef)  (4x4 tiles)
    {
        int tj = t >> 4, tk = t & 15;
        int k0 = tk * 4;
        float4 av  = *(const float4*)&sm.Av[k0];
        float4 wdv = *(const float4*)&sm.wd[k0];
        float4 wcv = *(const float4*)&sm.wc[k0];
        float acc[4][4];
        #pragma unroll
        for (int jj = 0; jj < 4; jj++) {
            int j = tj * 4 + jj;
            float djv = sm.dj[j], cjv = sm.cj[j];
            float4 bv = __ldg((const float4*)&d_Bm[(base + j) * 64 + k0]);
            acc[jj][0] = av.x + djv * wdv.x + cjv * wcv.x + bv.x;
            acc[jj][1] = av.y + djv * wdv.y + cjv * wcv.y + bv.y;
            acc[jj][2] = av.z + djv * wdv.z + cjv * wcv.z + bv.z;
            acc[jj][3] = av.w + djv * wdv.w + cjv * wcv.w + bv.w;
        }
        #pragma unroll
        for (int c4 = 0; c4 < 4; c4++) {
            float4 w0 = *(const float4*)&sm.W1ef[(c4 * 4 + 0) * 64 + k0];
            float4 w1 = *(const float4*)&sm.W1ef[(c4 * 4 + 1) * 64 + k0];
            float4 w2 = *(const float4*)&sm.W1ef[(c4 * 4 + 2) * 64 + k0];
            float4 w3 = *(const float4*)&sm.W1ef[(c4 * 4 + 3) * 64 + k0];
            #pragma unroll
            for (int jj = 0; jj < 4; jj++) {
                float4 ev = *(const float4*)&sm.efr[(tj * 4 + jj) * 16 + c4 * 4];
                acc[jj][0] += ev.x * w0.x + ev.y * w1.x + ev.z * w2.x + ev.w * w3.x;
                acc[jj][1] += ev.x * w0.y + ev.y * w1.y + ev.z * w2.y + ev.w * w3.y;
                acc[jj][2] += ev.x * w0.z + ev.y * w1.z + ev.z * w2.z + ev.w * w3.z;
                acc[jj][3] += ev.x * w0.w + ev.y * w1.w + ev.z * w2.w + ev.w * w3.w;
            }
        }
        #pragma unroll
        for (int jj = 0; jj < 4; jj++) {
            float4 hv;
            hv.x = silu(acc[jj][0]); hv.y = silu(acc[jj][1]);
            hv.z = silu(acc[jj][2]); hv.w = silu(acc[jj][3]);
            *(float4*)&sm.h[(tj * 4 + jj) * 64 + k0] = hv;
        }
    }
    __syncthreads();

    // P1: weight table + genv = (h @ W2gv + b2gv) * env   (2x2 tiles)
    {
        int j = t >> 2, w = t & 3;
        sm.wts[t] = (w == 0) ? sm.env[j] : sm.env[j] * sm.rn[j * 3 + (w - 1)];
    }
    {
        int j0 = (t >> 3) * 2, vc0 = (t & 7) * 2;
        float a00 = 0.f, a01 = 0.f, a10 = 0.f, a11 = 0.f;
        #pragma unroll 4
        for (int k4 = 0; k4 < 16; k4++) {
            float4 h0 = *(const float4*)&sm.h[j0 * 64 + k4 * 4];
            float4 h1 = *(const float4*)&sm.h[(j0 + 1) * 64 + k4 * 4];
            float4 g0 = *(const float4*)&sm.W2gvT[vc0 * 64 + k4 * 4];
            float4 g1 = *(const float4*)&sm.W2gvT[(vc0 + 1) * 64 + k4 * 4];
            a00 += h0.x * g0.x + h0.y * g0.y + h0.z * g0.z + h0.w * g0.w;
            a01 += h0.x * g1.x + h0.y * g1.y + h0.z * g1.z + h0.w * g1.w;
            a10 += h1.x * g0.x + h1.y * g0.y + h1.z * g0.z + h1.w * g0.w;
            a11 += h1.x * g1.x + h1.y * g1.y + h1.z * g1.z + h1.w * g1.w;
        }
        float b0 = __ldg(&b2l[80 + vc0]), b1v = __ldg(&b2l[80 + vc0 + 1]);
        float e0 = sm.env[j0], e1 = sm.env[j0 + 1];
        sm.genv[j0 * 16 + vc0]           = (a00 + b0)  * e0;
        sm.genv[j0 * 16 + vc0 + 1]       = (a01 + b1v) * e0;
        sm.genv[(j0 + 1) * 16 + vc0]     = (a10 + b0)  * e1;
        sm.genv[(j0 + 1) * 16 + vc0 + 1] = (a11 + b1v) * e1;
    }
    __syncthreads();

    // P2: hw[w][k] = sum_j wts[j][w] h[j][k];  S[w] = sum_j wts[j][w]
    {
        int k = t & 63, w = t >> 6;
        float acc = 0.f;
        #pragma unroll 8
        for (int j = 0; j < 64; j++) acc += sm.wts[j * 4 + w] * sm.h[j * 64 + k];
        sm.hw[w * 64 + k] = acc;
    }
    if (t < 4) {
        float ss = 0.f;
        #pragma unroll 8
        for (int j = 0; j < 64; j++) ss += sm.wts[j * 4 + t];
        sm.S[t] = ss;
    }
    __syncthreads();

    // T1: s-update partials (4-way split-K, all 256 threads)
    {
        int part = t >> 6, k = t & 63;
        float acc = 0.f;
        #pragma unroll
        for (int q = 0; q < 16; q++) {
            int kp = part * 16 + q;
            acc += sm.hw[kp] * __ldg(&W2l[kp * 97 + k]);
        }
        sm.scratch[part * 64 + k] = acc;
    }
    __syncthreads();

    // T2: combine s; v-update; p-update
    float degi = d_deg[i];
    if (t < 64) {
        float sn = d_s[i * 64 + t] + sm.scratch[t] + sm.scratch[64 + t]
                 + sm.scratch[128 + t] + sm.scratch[192 + t] + __ldg(&b2l[t]) * sm.S[0];
        sm.snew[t] = sn;
        d_s[i * 64 + t] = sn;
    } else if (t < 112) {
        int idx = t - 64, dim = idx >> 4, vc = idx & 15;
        float acc = sm.S[1 + dim] * __ldg(&b2l[64 + vc]);
        #pragma unroll 8
        for (int kp = 0; kp < 64; kp++)
            acc += sm.hw[(1 + dim) * 64 + kp] * __ldg(&W2l[kp * 97 + 64 + vc]);
        float accv = 0.f;
        #pragma unroll 4
        for (int j = 0; j < 64; j++)
            accv += __ldg(&d_vbuf[cur][(base + j) * 48 + dim * 16 + vc]) * sm.genv[j * 16 + vc];
        d_vbuf[nxt][i * 48 + dim * 16 + vc] =
            d_vbuf[cur][i * 48 + dim * 16 + vc] + (acc + accv) / degi;
    } else if (t < 115) {
        int dim = t - 112;
        float acc = sm.S[1 + dim] * __ldg(&b2l[96]);
        #pragma unroll 8
        for (int kp = 0; kp < 64; kp++)
            acc += sm.hw[(1 + dim) * 64 + kp] * __ldg(&W2l[kp * 97 + 96]);
        d_pbuf[nxt][i * 3 + dim] = d_pbuf[cur][i * 3 + dim] + acc / degi;
    }
    __syncthreads();

    // fused node MLP (layers 0..L-2), 4-way split-K
    if (doMLP) {
        {
            int part = t >> 6, k = t & 63;
            float acc = 0.f;
            #pragma unroll
            for (int q = 0; q < 16; q++) {
                int c = part * 16 + q;
                acc += sm.snew[c] * __ldg(&Wm1[l * 4096 + c * 64 + k]);
            }
            sm.scratch[part * 64 + k] = acc;
        }
        __syncthreads();
        if (t < 64)
            sm.hm[t] = silu(sm.scratch[t] + sm.scratch[64 + t] + sm.scratch[128 + t]
                          + sm.scratch[192 + t] + __ldg(&bm1[l * 64 + t]));
        __syncthreads();
        {
            int part = t >> 6, k = t & 63;
            float acc = 0.f;
            #pragma unroll
            for (int q = 0; q < 16; q++) {
                int c = part * 16 + q;
                acc += sm.hm[c] * __ldg(&Wm2[l * 4096 + c * 64 + k]);
            }
            sm.scratch[part * 64 + k] = acc;
        }
        __syncthreads();
        if (t < 64) {
            float s2 = sm.snew[t] + sm.scratch[t] + sm.scratch[64 + t]
                     + sm.scratch[128 + t] + sm.scratch[192 + t] + __ldg(&bm2[l * 64 + t]);
            sm.snew[t] = s2;
            d_s[i * 64 + t] = s2;
        }
        __syncthreads();
    }

    // f = snew @ Wpre + bpre   (16-way split-K)
    {
        int out_ = t & 15, part = t >> 4;
        float acc = 0.f;
        #pragma unroll
        for (int q = 0; q < 4; q++) {
            int k = part * 4 + q;
            acc += sm.snew[k] * __ldg(&Wpre[l * 1024 + k * 16 + out_]);
        }
        sm.scratch[t] = acc;       // scratch[part*16 + out]
    }
    __syncthreads();
    if (t < 16) {
        float acc = __ldg(&bpre[l * 16 + t]);
        #pragma unroll
        for (int q = 0; q < 16; q++) acc += sm.scratch[q * 16 + t];
        d_f[i * 16 + t] = acc;
    }
}

// ---------------- edge MLP update + node-pre for next layer ----------------
__global__ void __launch_bounds__(128) k_edgepre(
    int l, int doPre, int nxt,
    const float* __restrict__ Wpost, const float* __restrict__ bpost,
    const float* __restrict__ W1, const float* __restrict__ b1,
    const float* __restrict__ ln_g, const float* __restrict__ ln_b) {
    int i = blockIdx.x, t = threadIdx.x;   // 512 x 128
    int g = i >> 6, il = i & 63;
    int base = g << 6;
    __shared__ float sf[1024];
    __shared__ float sWp[256];
    __shared__ float sbp[16];
    __shared__ float stmp[1024];
    __shared__ float sln[64];
    __shared__ float red[64];
    for (int idx = t; idx < 1024; idx += 128) sf[idx] = d_f[base * 16 + idx];
    for (int idx = t; idx < 256; idx += 128) sWp[idx] = __ldg(&Wpost[l * 256 + idx]);
    if (t < 16) sbp[t] = __ldg(&bpost[l * 16 + t]);
    __syncthreads();
    for (int idx = t; idx < 1024; idx += 128) {
        int j = idx >> 4, c = idx & 15;
        stmp[idx] = d_E[i * 1024 + idx] + silu(sf[il * 16 + c] + sf[j * 16 + c]);
    }
    __syncthreads();
    for (int idx = t; idx < 1024; idx += 128) {
        int j = idx >> 4, c2 = idx & 15;
        if (d_maskArr[i * 64 + j] > 0.0f) {
            float acc = sbp[c2];
            #pragma unroll
            for (int c = 0; c < 16; c++) acc += stmp[j * 16 + c] * sWp[c * 16 + c2];
            d_E[i * 1024 + j * 16 + c2] = acc;
        }
    }

    if (!doPre) return;
    int lp = l + 1;
    __syncthreads();

    // LayerNorm of s row i (64 values, block-wide reduces)
    float sv = (t < 64) ? d_s[i * 64 + t] : 0.0f;
    if (t < 64) red[t] = sv;
    __syncthreads();
    #pragma unroll
    for (int off = 32; off > 0; off >>= 1) {
        if (t < off) red[t] += red[t + off];
        __syncthreads();
    }
    float mu = red[0] * (1.0f / 64.0f);
    __syncthreads();
    float dv = sv - mu;
    if (t < 64) red[t] = dv * dv;
    __syncthreads();
    #pragma unroll
    for (int off = 32; off > 0; off >>= 1) {
        if (t < off) red[t] += red[t + off];
        __syncthreads();
    }
    float var = red[0] * (1.0f / 64.0f);
    __syncthreads();
    if (t < 64) {
        float y = dv * rsqrtf(var + 1e-6f) * __ldg(&ln_g[lp * 64 + t]) + __ldg(&ln_b[lp * 64 + t]);
        d_s[i * 64 + t] = y;
        sln[t] = y;
    }

    // v normalize (buffer nxt = cur of layer lp)
    float vl = (t < 48) ? d_vbuf[nxt][i * 48 + t] : 0.0f;
    if (t < 64) red[t] = vl * vl;
    __syncthreads();
    #pragma unroll
    for (int off = 32; off > 0; off >>= 1) {
        if (t < off) red[t] += red[t + off];
        __syncthreads();
    }
    float vnorm = sqrtf(red[0] * (1.0f / 16.0f) + 1e-6f);
    if (t < 48) d_vbuf[nxt][i * 48 + t] = vl / vnorm;
    __syncthreads();

    // A (with b1 folded) and B
    const float* W = W1 + lp * 146 * 64;
    if (t < 64) {
        float a = __ldg(&b1[lp * 64 + t]);
        #pragma unroll 8
        for (int c = 0; c < 64; c++) a += sln[c] * __ldg(&W[c * 64 + t]);
        d_A[i * 64 + t] = a;
    } else {
        int k = t - 64;
        float b = 0.f;
        #pragma unroll 8
        for (int c = 0; c < 64; c++) b += sln[c] * __ldg(&W[(64 + c) * 64 + k]);
        d_Bm[i * 64 + k] = b;
    }
}

// ---------------- gather outputs ----------------
__global__ void k_out(float* __restrict__ out, const int* __restrict__ eidx, int fin) {
    int idx = blockIdx.x * blockDim.x + threadIdx.x;
    if (idx < 32768) {
        out[idx] = d_s[idx];
    } else if (idx < 57344) {
        out[idx] = d_vbuf[fin][idx - 32768];
    } else if (idx < 573440) {
        int q = idx - 57344;
        int e = q >> 4, c = q & 15;
        int s_ = eidx[e], t_ = eidx[EGC + e];
        out[idx] = d_E[(s_ * 64 + (t_ & 63)) * 16 + c];
    } else if (idx < 574976) {
        out[idx] = d_pbuf[fin][idx - 573440];
    }
}

extern "C" void kernel_launch(void* const* d_in, const int* in_sizes, int n_in,
                              void* d_out, int out_size) {
    const float* s     = (const float*)d_in[0];
    const float* v     = (const float*)d_in[1];
    const float* p     = (const float*)d_in[2];
    const float* ea    = (const float*)d_in[3];
    const int*   eidx  = (const int*)d_in[4];
    const int*   batch = (const int*)d_in[5];
    const float* ln_g  = (const float*)d_in[6];
    const float* ln_b  = (const float*)d_in[7];
    const float* W1    = (const float*)d_in[8];
    const float* b1    = (const float*)d_in[9];
    const float* W2    = (const float*)d_in[10];
    const float* b2    = (const float*)d_in[11];
    const float* Wm1   = (const float*)d_in[12];
    const float* bm1   = (const float*)d_in[13];
    const float* Wm2   = (const float*)d_in[14];
    const float* bm2   = (const float*)d_in[15];
    const float* Wpre  = (const float*)d_in[16];
    const float* bpre  = (const float*)d_in[17];
    const float* Wpost = (const float*)d_in[18];
    const float* bpost = (const float*)d_in[19];
    float* out = (float*)d_out;

    k_init<<<NN, 64>>>(s, v, p, batch, W1, b1, ln_g, ln_b);
    k_scatter<<<(EGC * 16 + 255) / 256, 256>>>(ea, eidx);

    int cur = 0;
    for (int l = 0; l < LL; l++) {
        k_pair<<<NN, 256>>>(l, cur, (l < LL - 1) ? 1 : 0,
                            W1, W2, b2, Wm1, bm1, Wm2, bm2, Wpre, bpre);
        k_edgepre<<<NN, 128>>>(l, (l < LL - 1) ? 1 : 0, cur ^ 1,
                               Wpost, bpost, W1, b1, ln_g, ln_b);
        cur ^= 1;
    }
    k_out<<<(574976 + 255) / 256, 256>>>(out, eidx, cur);
}